// round 7
// baseline (speedup 1.0000x reference)
#include <cuda_runtime.h>
#include <cuda_fp16.h>

// Factorized ray-marching: x@W1+b1 = p1 + alpha*u.
// R7: fast prep (parallel p1 reduction), gemm with batched B-frag loads,
// iter kernel with slim hot-loop register set (r/norm/output after the loop).

#define D_DIM 128
#define H_DIM 256
#define KT    8
#define NT    32
#define WROWS 16
#define WARPS 4
#define BROWS (WROWS * WARPS)
#define UPAD  (H_DIM + 8)
#define B_MAX 32768

__device__ float   g_p1[H_DIM];
__device__ __half2 g_p1h2[H_DIM / 2];
__device__ __half2 g_w2h2[H_DIM / 2];
__device__ uint2   g_Bfrag[KT * NT * 32];
__device__ __half  g_u[(size_t)B_MAX * H_DIM];

static __device__ __forceinline__ float tanh_fast(float x) {
    float y; asm("tanh.approx.f32 %0, %1;" : "=f"(y) : "f"(x)); return y;
}
static __device__ __forceinline__ __half2 tanh2_fast(__half2 x) {
    __half2 y;
    asm("tanh.approx.f16x2 %0, %1;" : "=r"(*(unsigned*)&y) : "r"(*(unsigned*)&x));
    return y;
}
static __device__ __forceinline__ unsigned h2bits(__half2 v) { return *(unsigned*)&v; }
static __device__ __forceinline__ unsigned hmul2b(unsigned a, __half2 s) {
    __half2 va = *(__half2*)&a;
    __half2 r = __hmul2(va, s);
    return *(unsigned*)&r;
}
static __device__ __forceinline__ void mma16816(float& c0, float& c1, float& c2, float& c3,
                                                unsigned a0, unsigned a1, unsigned a2, unsigned a3,
                                                unsigned b0, unsigned b1) {
    asm volatile("mma.sync.aligned.m16n8k16.row.col.f32.f16.f16.f32 "
                 "{%0,%1,%2,%3}, {%4,%5,%6,%7}, {%8,%9}, {%0,%1,%2,%3};"
                 : "+f"(c0), "+f"(c1), "+f"(c2), "+f"(c3)
                 : "r"(a0), "r"(a1), "r"(a2), "r"(a3), "r"(b0), "r"(b1));
}

// prep (grid 9, block 1024): block 0 -> p1 via 4-way d-split reduction;
// blocks 1..8 -> W1 B-fragment packing (8192 entries, one per thread).
__global__ __launch_bounds__(1024)
void prep_kernel(const float* __restrict__ pivot,
                 const float* __restrict__ W1,
                 const float* __restrict__ b1,
                 const float* __restrict__ w2) {
    if (blockIdx.x == 0) {
        __shared__ float red[4][H_DIM];
        __shared__ float sp1[H_DIM];
        const int j  = threadIdx.x & 255;
        const int dg = threadIdx.x >> 8;          // 0..3
        float s = 0.f;
        const int d0 = dg * 32;
#pragma unroll 8
        for (int d = d0; d < d0 + 32; ++d)
            s = fmaf(pivot[d], W1[(size_t)d * H_DIM + j], s);
        red[dg][j] = s;
        __syncthreads();
        if (dg == 0) {
            float v = red[0][j] + red[1][j] + red[2][j] + red[3][j] + b1[j];
            g_p1[j] = v;
            sp1[j] = v;
        }
        __syncthreads();
        if (threadIdx.x < H_DIM / 2) {
            g_p1h2[threadIdx.x] = __floats2half2_rn(sp1[2 * threadIdx.x],
                                                    sp1[2 * threadIdx.x + 1]);
            g_w2h2[threadIdx.x] = __floats2half2_rn(w2[2 * threadIdx.x],
                                                    w2[2 * threadIdx.x + 1]);
        }
    } else {
        const int e = (blockIdx.x - 1) * 1024 + threadIdx.x;   // 0..8191
        const int tile = e >> 5;
        const int lane = e & 31;
        const int kt = tile / NT;
        const int nt = tile % NT;
        const int g = lane >> 2, t4 = lane & 3;
        const int k0 = kt * 16 + t4 * 2;
        const int col = nt * 8 + g;
        __half2 b0v = __floats2half2_rn(W1[(size_t)k0 * H_DIM + col],
                                        W1[(size_t)(k0 + 1) * H_DIM + col]);
        __half2 b1v = __floats2half2_rn(W1[(size_t)(k0 + 8) * H_DIM + col],
                                        W1[(size_t)(k0 + 9) * H_DIM + col]);
        g_Bfrag[tile * 32 + lane] = make_uint2(h2bits(b0v), h2bits(b1v));
    }
}

// ===================== Kernel 1: HMMA GEMM, u -> gmem =====================
__global__ __launch_bounds__(128)
void gemm_kernel(const float* __restrict__ r, int B) {
    __shared__ __half u_sh[BROWS][UPAD];

    const int lane = threadIdx.x & 31;
    const int wib  = threadIdx.x >> 5;
    const int row0 = (blockIdx.x * WARPS + wib) * WROWS;
    const int lrow0 = wib * WROWS;
    if (row0 < B) {
        const int g4 = lane >> 2, t4 = lane & 3;
        const float* pA = r + (size_t)(row0 + g4) * D_DIM;
        const float* pB = pA + (size_t)8 * D_DIM;

        unsigned a0[KT], a1[KT], a2[KT], a3[KT];
        float sl = 0.f, sh = 0.f;
#pragma unroll
        for (int kt = 0; kt < KT; ++kt) {
            const int base = kt * 16 + t4 * 2;
            float2 v0 = *(const float2*)(pA + base);
            float2 v1 = *(const float2*)(pB + base);
            float2 v2 = *(const float2*)(pA + base + 8);
            float2 v3 = *(const float2*)(pB + base + 8);
            sl = fmaf(v0.x, v0.x, fmaf(v0.y, v0.y, fmaf(v2.x, v2.x, fmaf(v2.y, v2.y, sl))));
            sh = fmaf(v1.x, v1.x, fmaf(v1.y, v1.y, fmaf(v3.x, v3.x, fmaf(v3.y, v3.y, sh))));
            a0[kt] = h2bits(__floats2half2_rn(v0.x, v0.y));
            a1[kt] = h2bits(__floats2half2_rn(v1.x, v1.y));
            a2[kt] = h2bits(__floats2half2_rn(v2.x, v2.y));
            a3[kt] = h2bits(__floats2half2_rn(v3.x, v3.y));
        }
        sl += __shfl_xor_sync(0xffffffffu, sl, 1);
        sl += __shfl_xor_sync(0xffffffffu, sl, 2);
        sh += __shfl_xor_sync(0xffffffffu, sh, 1);
        sh += __shfl_xor_sync(0xffffffffu, sh, 2);
        const __half2 il2 = __float2half2_rn(rsqrtf(sl));
        const __half2 ih2 = __float2half2_rn(rsqrtf(sh));
#pragma unroll
        for (int kt = 0; kt < KT; ++kt) {
            a0[kt] = hmul2b(a0[kt], il2);
            a2[kt] = hmul2b(a2[kt], il2);
            a1[kt] = hmul2b(a1[kt], ih2);
            a3[kt] = hmul2b(a3[kt], ih2);
        }

#pragma unroll
        for (int c = 0; c < 4; ++c) {
            float acc[8][4];
#pragma unroll
            for (int t = 0; t < 8; ++t)
#pragma unroll
                for (int q = 0; q < 4; ++q) acc[t][q] = 0.f;
#pragma unroll
            for (int kt = 0; kt < KT; ++kt) {
                // batch all 8 B-fragment loads, then 8 MMAs (MLP=8)
                uint2 bf[8];
                const uint2* bb = g_Bfrag + (size_t)(kt * NT + c * 8) * 32 + lane;
#pragma unroll
                for (int t = 0; t < 8; ++t) bf[t] = __ldg(bb + t * 32);
#pragma unroll
                for (int t = 0; t < 8; ++t)
                    mma16816(acc[t][0], acc[t][1], acc[t][2], acc[t][3],
                             a0[kt], a1[kt], a2[kt], a3[kt], bf[t].x, bf[t].y);
            }
#pragma unroll
            for (int t = 0; t < 8; ++t) {
                const int col = (c * 8 + t) * 8 + t4 * 2;
                *(__half2*)&u_sh[lrow0 + g4][col]     = __floats2half2_rn(acc[t][0], acc[t][1]);
                *(__half2*)&u_sh[lrow0 + g4 + 8][col] = __floats2half2_rn(acc[t][2], acc[t][3]);
            }
        }
    }
    __syncthreads();

    const int base_row = blockIdx.x * BROWS;
    uint4* gu4 = (uint4*)g_u;
#pragma unroll
    for (int it = 0; it < 16; ++it) {
        const int li = it * 128 + threadIdx.x;
        const int rw = li >> 5;
        const int q  = li & 31;
        if (base_row + rw < B)
            gu4[(size_t)(base_row + rw) * 32 + q] = *(const uint4*)&u_sh[rw][q * 8];
    }
}

// ===================== Kernel 2: 20-step recurrence =====================
__global__ __launch_bounds__(256)
void iter_kernel(const float* __restrict__ r,
                 const float* __restrict__ s_in,
                 const float* __restrict__ pivot,
                 const float* __restrict__ b2,
                 const int* __restrict__ n_iter_ptr,
                 float* __restrict__ out,
                 int B) {
    const int lane = threadIdx.x & 31;
    const int wib  = threadIdx.x >> 5;
    const int gB = lane >> 3, lB = lane & 7;
    const int row = blockIdx.x * 32 + wib * 4 + gB;
    if (row >= B) return;

    // hot-loop inputs only: u, p1, w2, b2
    __half2 u2[16];
    {
        const uint4* up = (const uint4*)(g_u + (size_t)row * H_DIM) + lB * 4;
#pragma unroll
        for (int v = 0; v < 4; ++v) {
            uint4 w = __ldg(up + v);
            u2[v * 4 + 0] = *(__half2*)&w.x;
            u2[v * 4 + 1] = *(__half2*)&w.y;
            u2[v * 4 + 2] = *(__half2*)&w.z;
            u2[v * 4 + 3] = *(__half2*)&w.w;
        }
    }
    __half2 p12[16], w22[16];
    {
        const uint4* pp = (const uint4*)g_p1h2 + lB * 4;
        const uint4* wp = (const uint4*)g_w2h2 + lB * 4;
#pragma unroll
        for (int v = 0; v < 4; ++v) {
            uint4 a = __ldg(pp + v), b = __ldg(wp + v);
            p12[v * 4 + 0] = *(__half2*)&a.x; p12[v * 4 + 1] = *(__half2*)&a.y;
            p12[v * 4 + 2] = *(__half2*)&a.z; p12[v * 4 + 3] = *(__half2*)&a.w;
            w22[v * 4 + 0] = *(__half2*)&b.x; w22[v * 4 + 1] = *(__half2*)&b.y;
            w22[v * 4 + 2] = *(__half2*)&b.z; w22[v * 4 + 3] = *(__half2*)&b.w;
        }
    }

    const float b2v = b2[0];
    const int n = n_iter_ptr ? *n_iter_ptr : 20;
    const __half2 h2z = __floats2half2_rn(0.f, 0.f);

    float alpha = 0.f;
    for (int it = 0; it < n; ++it) {
        const __half2 a2h = __float2half2_rn(alpha);
        __half2 acc2a = h2z, acc2b = h2z;
#pragma unroll
        for (int q = 0; q < 16; q += 2) {
            __half2 za = __hfma2(a2h, u2[q],     p12[q]);
            __half2 zb = __hfma2(a2h, u2[q + 1], p12[q + 1]);
            acc2a = __hfma2(tanh2_fast(za), w22[q],     acc2a);
            acc2b = __hfma2(tanh2_fast(zb), w22[q + 1], acc2b);
        }
        __half2 acc2 = __hadd2(acc2a, acc2b);
        float accf = __low2float(acc2) + __high2float(acc2);
        accf += __shfl_xor_sync(0xffffffffu, accf, 1);
        accf += __shfl_xor_sync(0xffffffffu, accf, 2);
        accf += __shfl_xor_sync(0xffffffffu, accf, 4);
        alpha += 0.05f * (1.0f + tanh_fast(accf + b2v));
    }

    // cold tail: r row, norm, sigmoid, output
    const float4* rv4 = (const float4*)(r + (size_t)row * D_DIM) + lB * 4;
    float4 rv[4];
    float ss = 0.f;
#pragma unroll
    for (int j = 0; j < 4; ++j) {
        rv[j] = rv4[j];
        ss = fmaf(rv[j].x, rv[j].x, fmaf(rv[j].y, rv[j].y,
             fmaf(rv[j].z, rv[j].z, fmaf(rv[j].w, rv[j].w, ss))));
    }
    ss += __shfl_xor_sync(0xffffffffu, ss, 1);
    ss += __shfl_xor_sync(0xffffffffu, ss, 2);
    ss += __shfl_xor_sync(0xffffffffu, ss, 4);
    const float inv_norm = rsqrtf(ss);

    const float sv = s_in[row];
    const float sig = 1.0f / (1.0f + __expf(-sv));
    const float fscale = sig * alpha * inv_norm;

    const float4* pv4 = (const float4*)pivot + lB * 4;
    float4* ov4 = (float4*)(out + (size_t)row * D_DIM) + lB * 4;
#pragma unroll
    for (int jj = 0; jj < 4; ++jj) {
        float4 pv = pv4[jj];
        float4 o;
        o.x = fmaf(fscale, rv[jj].x, pv.x);
        o.y = fmaf(fscale, rv[jj].y, pv.y);
        o.z = fmaf(fscale, rv[jj].z, pv.z);
        o.w = fmaf(fscale, rv[jj].w, pv.w);
        ov4[jj] = o;
    }
}

extern "C" void kernel_launch(void* const* d_in, const int* in_sizes, int n_in,
                              void* d_out, int out_size) {
    const float* r     = (const float*)d_in[0];   // [B,128]
    const float* s     = (const float*)d_in[1];   // [B,1]
    const float* pivot = (const float*)d_in[2];   // [128]
    const float* W1    = (const float*)d_in[3];   // [128,256]
    const float* b1    = (const float*)d_in[4];   // [256]
    const float* w2    = (const float*)d_in[5];   // [256]
    const float* b2    = (const float*)d_in[6];   // [1]
    const int* n_iter  = (n_in > 7) ? (const int*)d_in[7] : nullptr;
    float* out = (float*)d_out;

    const int B = in_sizes[0] / D_DIM;

    prep_kernel<<<9, 1024>>>(pivot, W1, b1, w2);

    const int gblocks = (B + BROWS - 1) / BROWS;
    gemm_kernel<<<gblocks, 128>>>(r, B);

    const int iblocks = (B + 31) / 32;
    iter_kernel<<<iblocks, 256>>>(r, s, pivot, b2, n_iter, out, B);
}

// round 8
// speedup vs baseline: 1.3282x; 1.3282x over previous
#include <cuda_runtime.h>
#include <cuda_fp16.h>

// Factorized ray-marching: x@W1+b1 = p1 + alpha*u.
// R8: single fused main kernel at full parallelism. Block = 32 rows, 8 warps.
// GEMM phase: warp = 16 rows x 64 cols (HMMA m16n8k16), u -> smem.
// Iter phase: 4 rows/warp, 8-lane groups, f16x2 tanh, 3-shfl reduction.
// 8192 warps for both phases; no u gmem round-trip.

#define D_DIM 128
#define H_DIM 256
#define KT    8
#define NT    32
#define UPAD  (H_DIM + 8)

__device__ __half2 g_p1h2[H_DIM / 2];
__device__ __half2 g_w2h2[H_DIM / 2];
__device__ uint2   g_Bfrag[KT * NT * 32];   // 64 KB: W1 in HMMA B-fragment layout

static __device__ __forceinline__ float tanh_fast(float x) {
    float y; asm("tanh.approx.f32 %0, %1;" : "=f"(y) : "f"(x)); return y;
}
static __device__ __forceinline__ __half2 tanh2_fast(__half2 x) {
    __half2 y;
    asm("tanh.approx.f16x2 %0, %1;" : "=r"(*(unsigned*)&y) : "r"(*(unsigned*)&x));
    return y;
}
static __device__ __forceinline__ unsigned h2bits(__half2 v) { return *(unsigned*)&v; }
static __device__ __forceinline__ unsigned hmul2b(unsigned a, __half2 s) {
    __half2 va = *(__half2*)&a;
    __half2 r = __hmul2(va, s);
    return *(unsigned*)&r;
}
static __device__ __forceinline__ void mma16816(float& c0, float& c1, float& c2, float& c3,
                                                unsigned a0, unsigned a1, unsigned a2, unsigned a3,
                                                unsigned b0, unsigned b1) {
    asm volatile("mma.sync.aligned.m16n8k16.row.col.f32.f16.f16.f32 "
                 "{%0,%1,%2,%3}, {%4,%5,%6,%7}, {%8,%9}, {%0,%1,%2,%3};"
                 : "+f"(c0), "+f"(c1), "+f"(c2), "+f"(c3)
                 : "r"(a0), "r"(a1), "r"(a2), "r"(a3), "r"(b0), "r"(b1));
}

// prep (grid 9, block 1024): block 0 -> p1 (4-way d-split reduction) + half
// copies; blocks 1..8 -> W1 B-fragment packing.
__global__ __launch_bounds__(1024)
void prep_kernel(const float* __restrict__ pivot,
                 const float* __restrict__ W1,
                 const float* __restrict__ b1,
                 const float* __restrict__ w2) {
    if (blockIdx.x == 0) {
        __shared__ float red[4][H_DIM];
        __shared__ float sp1[H_DIM];
        const int j  = threadIdx.x & 255;
        const int dg = threadIdx.x >> 8;
        float s = 0.f;
        const int d0 = dg * 32;
#pragma unroll 8
        for (int d = d0; d < d0 + 32; ++d)
            s = fmaf(pivot[d], W1[(size_t)d * H_DIM + j], s);
        red[dg][j] = s;
        __syncthreads();
        if (dg == 0)
            sp1[j] = red[0][j] + red[1][j] + red[2][j] + red[3][j] + b1[j];
        __syncthreads();
        if (threadIdx.x < H_DIM / 2) {
            g_p1h2[threadIdx.x] = __floats2half2_rn(sp1[2 * threadIdx.x],
                                                    sp1[2 * threadIdx.x + 1]);
            g_w2h2[threadIdx.x] = __floats2half2_rn(w2[2 * threadIdx.x],
                                                    w2[2 * threadIdx.x + 1]);
        }
    } else {
        const int e = (blockIdx.x - 1) * 1024 + threadIdx.x;   // 0..8191
        const int tile = e >> 5;
        const int lane = e & 31;
        const int kt = tile / NT;
        const int nt = tile % NT;
        const int g = lane >> 2, t4 = lane & 3;
        const int k0 = kt * 16 + t4 * 2;
        const int col = nt * 8 + g;
        __half2 b0v = __floats2half2_rn(W1[(size_t)k0 * H_DIM + col],
                                        W1[(size_t)(k0 + 1) * H_DIM + col]);
        __half2 b1v = __floats2half2_rn(W1[(size_t)(k0 + 8) * H_DIM + col],
                                        W1[(size_t)(k0 + 9) * H_DIM + col]);
        g_Bfrag[tile * 32 + lane] = make_uint2(h2bits(b0v), h2bits(b1v));
    }
}

// ===================== fused main kernel: block = 32 rows =====================
__global__ __launch_bounds__(256)
void main_kernel(const float* __restrict__ r,
                 const float* __restrict__ s_in,
                 const float* __restrict__ pivot,
                 const float* __restrict__ b2,
                 const int* __restrict__ n_iter_ptr,
                 float* __restrict__ out,
                 int B) {
    __shared__ __half u_sh[32][UPAD];     // 32 x 264 halves = 16.5 KB

    const int lane = threadIdx.x & 31;
    const int wib  = threadIdx.x >> 5;
    const int base_row = blockIdx.x * 32;
    const bool full = (base_row + 32 <= B);   // B is a multiple of 32 in this dataset

    // ---------- Phase A: GEMM. warp = 16 rows x 64 cols ----------
    if (full) {
        const int rowg = (wib >> 2) * 16;          // 0 or 16
        const int ntg  = (wib & 3) * 8;            // first of 8 n-tiles
        const int g4 = lane >> 2, t4 = lane & 3;
        const float* pA = r + (size_t)(base_row + rowg + g4) * D_DIM;
        const float* pB = pA + (size_t)8 * D_DIM;

        unsigned a0[KT], a1[KT], a2[KT], a3[KT];
        float sl = 0.f, sh = 0.f;
#pragma unroll
        for (int kt = 0; kt < KT; ++kt) {
            const int base = kt * 16 + t4 * 2;
            float2 v0 = *(const float2*)(pA + base);
            float2 v1 = *(const float2*)(pB + base);
            float2 v2 = *(const float2*)(pA + base + 8);
            float2 v3 = *(const float2*)(pB + base + 8);
            sl = fmaf(v0.x, v0.x, fmaf(v0.y, v0.y, fmaf(v2.x, v2.x, fmaf(v2.y, v2.y, sl))));
            sh = fmaf(v1.x, v1.x, fmaf(v1.y, v1.y, fmaf(v3.x, v3.x, fmaf(v3.y, v3.y, sh))));
            a0[kt] = h2bits(__floats2half2_rn(v0.x, v0.y));
            a1[kt] = h2bits(__floats2half2_rn(v1.x, v1.y));
            a2[kt] = h2bits(__floats2half2_rn(v2.x, v2.y));
            a3[kt] = h2bits(__floats2half2_rn(v3.x, v3.y));
        }
        sl += __shfl_xor_sync(0xffffffffu, sl, 1);
        sl += __shfl_xor_sync(0xffffffffu, sl, 2);
        sh += __shfl_xor_sync(0xffffffffu, sh, 1);
        sh += __shfl_xor_sync(0xffffffffu, sh, 2);
        const __half2 il2 = __float2half2_rn(rsqrtf(sl));
        const __half2 ih2 = __float2half2_rn(rsqrtf(sh));
#pragma unroll
        for (int kt = 0; kt < KT; ++kt) {
            a0[kt] = hmul2b(a0[kt], il2);
            a2[kt] = hmul2b(a2[kt], il2);
            a1[kt] = hmul2b(a1[kt], ih2);
            a3[kt] = hmul2b(a3[kt], ih2);
        }

        // two passes of 4 n-tiles (keeps accumulator live-set at 16 regs)
#pragma unroll
        for (int half = 0; half < 2; ++half) {
            float acc[4][4];
#pragma unroll
            for (int t = 0; t < 4; ++t)
#pragma unroll
                for (int q = 0; q < 4; ++q) acc[t][q] = 0.f;
#pragma unroll
            for (int kt = 0; kt < KT; ++kt) {
                uint2 bf[4];
                const uint2* bb = g_Bfrag + (size_t)(kt * NT + ntg + half * 4) * 32 + lane;
#pragma unroll
                for (int t = 0; t < 4; ++t) bf[t] = __ldg(bb + t * 32);
#pragma unroll
                for (int t = 0; t < 4; ++t)
                    mma16816(acc[t][0], acc[t][1], acc[t][2], acc[t][3],
                             a0[kt], a1[kt], a2[kt], a3[kt], bf[t].x, bf[t].y);
            }
#pragma unroll
            for (int t = 0; t < 4; ++t) {
                const int col = (ntg + half * 4 + t) * 8 + t4 * 2;
                *(__half2*)&u_sh[rowg + g4][col]     = __floats2half2_rn(acc[t][0], acc[t][1]);
                *(__half2*)&u_sh[rowg + g4 + 8][col] = __floats2half2_rn(acc[t][2], acc[t][3]);
            }
        }
    }
    __syncthreads();

    // ---------- Phase B: 20-step recurrence, 4 rows/warp ----------
    const int gB = lane >> 3, lB = lane & 7;
    const int lrow = wib * 4 + gB;
    const int row = base_row + lrow;
    if (!full || row >= B) { if (row >= B) return; }
    if (row >= B) return;

    __half2 u2[16];
    {
        const uint4* up = (const uint4*)(&u_sh[lrow][lB * 32]);
#pragma unroll
        for (int v = 0; v < 4; ++v) {
            uint4 w = up[v];
            u2[v * 4 + 0] = *(__half2*)&w.x;
            u2[v * 4 + 1] = *(__half2*)&w.y;
            u2[v * 4 + 2] = *(__half2*)&w.z;
            u2[v * 4 + 3] = *(__half2*)&w.w;
        }
    }
    __half2 p12[16], w22[16];
    {
        const uint4* pp = (const uint4*)g_p1h2 + lB * 4;
        const uint4* wp = (const uint4*)g_w2h2 + lB * 4;
#pragma unroll
        for (int v = 0; v < 4; ++v) {
            uint4 a = __ldg(pp + v), b = __ldg(wp + v);
            p12[v * 4 + 0] = *(__half2*)&a.x; p12[v * 4 + 1] = *(__half2*)&a.y;
            p12[v * 4 + 2] = *(__half2*)&a.z; p12[v * 4 + 3] = *(__half2*)&a.w;
            w22[v * 4 + 0] = *(__half2*)&b.x; w22[v * 4 + 1] = *(__half2*)&b.y;
            w22[v * 4 + 2] = *(__half2*)&b.z; w22[v * 4 + 3] = *(__half2*)&b.w;
        }
    }

    const float b2v = b2[0];
    const int n = n_iter_ptr ? *n_iter_ptr : 20;
    const __half2 h2z = __floats2half2_rn(0.f, 0.f);

    float alpha = 0.f;
    for (int it = 0; it < n; ++it) {
        const __half2 a2h = __float2half2_rn(alpha);
        __half2 acc2a = h2z, acc2b = h2z;
#pragma unroll
        for (int q = 0; q < 16; q += 2) {
            __half2 za = __hfma2(a2h, u2[q],     p12[q]);
            __half2 zb = __hfma2(a2h, u2[q + 1], p12[q + 1]);
            acc2a = __hfma2(tanh2_fast(za), w22[q],     acc2a);
            acc2b = __hfma2(tanh2_fast(zb), w22[q + 1], acc2b);
        }
        __half2 acc2 = __hadd2(acc2a, acc2b);
        float accf = __low2float(acc2) + __high2float(acc2);
        accf += __shfl_xor_sync(0xffffffffu, accf, 1);
        accf += __shfl_xor_sync(0xffffffffu, accf, 2);
        accf += __shfl_xor_sync(0xffffffffu, accf, 4);
        alpha += 0.05f * (1.0f + tanh_fast(accf + b2v));
    }

    // tail: r reload, norm, sigmoid, output (lane owns dims 16*lB..16*lB+15)
    const float4* rv4 = (const float4*)(r + (size_t)row * D_DIM) + lB * 4;
    float4 rv[4];
    float ss = 0.f;
#pragma unroll
    for (int j = 0; j < 4; ++j) {
        rv[j] = rv4[j];
        ss = fmaf(rv[j].x, rv[j].x, fmaf(rv[j].y, rv[j].y,
             fmaf(rv[j].z, rv[j].z, fmaf(rv[j].w, rv[j].w, ss))));
    }
    ss += __shfl_xor_sync(0xffffffffu, ss, 1);
    ss += __shfl_xor_sync(0xffffffffu, ss, 2);
    ss += __shfl_xor_sync(0xffffffffu, ss, 4);
    const float inv_norm = rsqrtf(ss);

    const float sv = s_in[row];
    const float sig = 1.0f / (1.0f + __expf(-sv));
    const float fscale = sig * alpha * inv_norm;

    const float4* pv4 = (const float4*)pivot + lB * 4;
    float4* ov4 = (float4*)(out + (size_t)row * D_DIM) + lB * 4;
#pragma unroll
    for (int jj = 0; jj < 4; ++jj) {
        float4 pv = pv4[jj];
        float4 o;
        o.x = fmaf(fscale, rv[jj].x, pv.x);
        o.y = fmaf(fscale, rv[jj].y, pv.y);
        o.z = fmaf(fscale, rv[jj].z, pv.z);
        o.w = fmaf(fscale, rv[jj].w, pv.w);
        ov4[jj] = o;
    }
}

extern "C" void kernel_launch(void* const* d_in, const int* in_sizes, int n_in,
                              void* d_out, int out_size) {
    const float* r     = (const float*)d_in[0];   // [B,128]
    const float* s     = (const float*)d_in[1];   // [B,1]
    const float* pivot = (const float*)d_in[2];   // [128]
    const float* W1    = (const float*)d_in[3];   // [128,256]
    const float* b1    = (const float*)d_in[4];   // [256]
    const float* w2    = (const float*)d_in[5];   // [256]
    const float* b2    = (const float*)d_in[6];   // [1]
    const int* n_iter  = (n_in > 7) ? (const int*)d_in[7] : nullptr;
    float* out = (float*)d_out;

    const int B = in_sizes[0] / D_DIM;

    prep_kernel<<<9, 1024>>>(pivot, W1, b1, w2);

    const int blocks = (B + 31) / 32;
    main_kernel<<<blocks, 256>>>(r, s, pivot, b2, n_iter, out, B);
}

// round 9
// speedup vs baseline: 1.4183x; 1.0678x over previous
#include <cuda_runtime.h>
#include <cuda_fp16.h>

// Factorized ray-marching: x@W1+b1 = p1 + alpha*u.
// R9: R8 fused kernel + forced 4 blocks/SM (<=64 regs) + half-block named
// barriers between GEMM and iter phases (warps 0-3 and 4-7 are independent).

#define D_DIM 128
#define H_DIM 256
#define KT    8
#define NT    32
#define UPAD  (H_DIM + 8)

__device__ __half2 g_p1h2[H_DIM / 2];
__device__ __half2 g_w2h2[H_DIM / 2];
__device__ uint2   g_Bfrag[KT * NT * 32];   // 64 KB: W1 in HMMA B-fragment layout

static __device__ __forceinline__ float tanh_fast(float x) {
    float y; asm("tanh.approx.f32 %0, %1;" : "=f"(y) : "f"(x)); return y;
}
static __device__ __forceinline__ __half2 tanh2_fast(__half2 x) {
    __half2 y;
    asm("tanh.approx.f16x2 %0, %1;" : "=r"(*(unsigned*)&y) : "r"(*(unsigned*)&x));
    return y;
}
static __device__ __forceinline__ unsigned h2bits(__half2 v) { return *(unsigned*)&v; }
static __device__ __forceinline__ unsigned hmul2b(unsigned a, __half2 s) {
    __half2 va = *(__half2*)&a;
    __half2 r = __hmul2(va, s);
    return *(unsigned*)&r;
}
static __device__ __forceinline__ void mma16816(float& c0, float& c1, float& c2, float& c3,
                                                unsigned a0, unsigned a1, unsigned a2, unsigned a3,
                                                unsigned b0, unsigned b1) {
    asm volatile("mma.sync.aligned.m16n8k16.row.col.f32.f16.f16.f32 "
                 "{%0,%1,%2,%3}, {%4,%5,%6,%7}, {%8,%9}, {%0,%1,%2,%3};"
                 : "+f"(c0), "+f"(c1), "+f"(c2), "+f"(c3)
                 : "r"(a0), "r"(a1), "r"(a2), "r"(a3), "r"(b0), "r"(b1));
}

// prep (grid 9, block 1024): block 0 -> p1 (4-way d-split reduction) + half
// copies; blocks 1..8 -> W1 B-fragment packing.
__global__ __launch_bounds__(1024)
void prep_kernel(const float* __restrict__ pivot,
                 const float* __restrict__ W1,
                 const float* __restrict__ b1,
                 const float* __restrict__ w2) {
    if (blockIdx.x == 0) {
        __shared__ float red[4][H_DIM];
        __shared__ float sp1[H_DIM];
        const int j  = threadIdx.x & 255;
        const int dg = threadIdx.x >> 8;
        float s = 0.f;
        const int d0 = dg * 32;
#pragma unroll 8
        for (int d = d0; d < d0 + 32; ++d)
            s = fmaf(pivot[d], W1[(size_t)d * H_DIM + j], s);
        red[dg][j] = s;
        __syncthreads();
        if (dg == 0)
            sp1[j] = red[0][j] + red[1][j] + red[2][j] + red[3][j] + b1[j];
        __syncthreads();
        if (threadIdx.x < H_DIM / 2) {
            g_p1h2[threadIdx.x] = __floats2half2_rn(sp1[2 * threadIdx.x],
                                                    sp1[2 * threadIdx.x + 1]);
            g_w2h2[threadIdx.x] = __floats2half2_rn(w2[2 * threadIdx.x],
                                                    w2[2 * threadIdx.x + 1]);
        }
    } else {
        const int e = (blockIdx.x - 1) * 1024 + threadIdx.x;   // 0..8191
        const int tile = e >> 5;
        const int lane = e & 31;
        const int kt = tile / NT;
        const int nt = tile % NT;
        const int g = lane >> 2, t4 = lane & 3;
        const int k0 = kt * 16 + t4 * 2;
        const int col = nt * 8 + g;
        __half2 b0v = __floats2half2_rn(W1[(size_t)k0 * H_DIM + col],
                                        W1[(size_t)(k0 + 1) * H_DIM + col]);
        __half2 b1v = __floats2half2_rn(W1[(size_t)(k0 + 8) * H_DIM + col],
                                        W1[(size_t)(k0 + 9) * H_DIM + col]);
        g_Bfrag[tile * 32 + lane] = make_uint2(h2bits(b0v), h2bits(b1v));
    }
}

// ===================== fused main kernel: block = 32 rows =====================
__global__ __launch_bounds__(256, 4)
void main_kernel(const float* __restrict__ r,
                 const float* __restrict__ s_in,
                 const float* __restrict__ pivot,
                 const float* __restrict__ b2,
                 const int* __restrict__ n_iter_ptr,
                 float* __restrict__ out,
                 int B) {
    __shared__ __half u_sh[32][UPAD];     // 32 x 264 halves = 16.5 KB

    const int lane = threadIdx.x & 31;
    const int wib  = threadIdx.x >> 5;
    const int half_id = wib >> 2;              // 0 or 1 (16-row half of the block)
    const int base_row = blockIdx.x * 32;

    // ---------- Phase A: GEMM. warp = 16 rows x 64 cols ----------
    {
        const int rowg = half_id * 16;             // 0 or 16
        const int ntg  = (wib & 3) * 8;            // first of 8 n-tiles
        const int g4 = lane >> 2, t4 = lane & 3;
        const float* pA = r + (size_t)(base_row + rowg + g4) * D_DIM;
        const float* pB = pA + (size_t)8 * D_DIM;

        unsigned a0[KT], a1[KT], a2[KT], a3[KT];
        float sl = 0.f, sh = 0.f;
#pragma unroll
        for (int kt = 0; kt < KT; ++kt) {
            const int base = kt * 16 + t4 * 2;
            float2 v0 = *(const float2*)(pA + base);
            float2 v1 = *(const float2*)(pB + base);
            float2 v2 = *(const float2*)(pA + base + 8);
            float2 v3 = *(const float2*)(pB + base + 8);
            sl = fmaf(v0.x, v0.x, fmaf(v0.y, v0.y, fmaf(v2.x, v2.x, fmaf(v2.y, v2.y, sl))));
            sh = fmaf(v1.x, v1.x, fmaf(v1.y, v1.y, fmaf(v3.x, v3.x, fmaf(v3.y, v3.y, sh))));
            a0[kt] = h2bits(__floats2half2_rn(v0.x, v0.y));
            a1[kt] = h2bits(__floats2half2_rn(v1.x, v1.y));
            a2[kt] = h2bits(__floats2half2_rn(v2.x, v2.y));
            a3[kt] = h2bits(__floats2half2_rn(v3.x, v3.y));
        }
        sl += __shfl_xor_sync(0xffffffffu, sl, 1);
        sl += __shfl_xor_sync(0xffffffffu, sl, 2);
        sh += __shfl_xor_sync(0xffffffffu, sh, 1);
        sh += __shfl_xor_sync(0xffffffffu, sh, 2);
        const __half2 il2 = __float2half2_rn(rsqrtf(sl));
        const __half2 ih2 = __float2half2_rn(rsqrtf(sh));
#pragma unroll
        for (int kt = 0; kt < KT; ++kt) {
            a0[kt] = hmul2b(a0[kt], il2);
            a2[kt] = hmul2b(a2[kt], il2);
            a1[kt] = hmul2b(a1[kt], ih2);
            a3[kt] = hmul2b(a3[kt], ih2);
        }

        // two passes of 4 n-tiles (accumulator live-set 16 regs)
#pragma unroll
        for (int half = 0; half < 2; ++half) {
            float acc[4][4];
#pragma unroll
            for (int t = 0; t < 4; ++t)
#pragma unroll
                for (int q = 0; q < 4; ++q) acc[t][q] = 0.f;
#pragma unroll
            for (int kt = 0; kt < KT; ++kt) {
                uint2 bf[4];
                const uint2* bb = g_Bfrag + (size_t)(kt * NT + ntg + half * 4) * 32 + lane;
#pragma unroll
                for (int t = 0; t < 4; ++t) bf[t] = __ldg(bb + t * 32);
#pragma unroll
                for (int t = 0; t < 4; ++t)
                    mma16816(acc[t][0], acc[t][1], acc[t][2], acc[t][3],
                             a0[kt], a1[kt], a2[kt], a3[kt], bf[t].x, bf[t].y);
            }
#pragma unroll
            for (int t = 0; t < 4; ++t) {
                const int col = (ntg + half * 4 + t) * 8 + t4 * 2;
                *(__half2*)&u_sh[rowg + g4][col]     = __floats2half2_rn(acc[t][0], acc[t][1]);
                *(__half2*)&u_sh[rowg + g4 + 8][col] = __floats2half2_rn(acc[t][2], acc[t][3]);
            }
        }
    }
    // half-block barrier: warps 0-3 produce+consume rows 0-15; warps 4-7 rows 16-31
    asm volatile("bar.sync %0, 128;" :: "r"(1 + half_id) : "memory");

    // ---------- Phase B: 20-step recurrence, 4 rows/warp ----------
    const int gB = lane >> 3, lB = lane & 7;
    const int lrow = wib * 4 + gB;
    const int row = base_row + lrow;
    if (row >= B) return;

    __half2 u2[16];
    {
        const uint4* up = (const uint4*)(&u_sh[lrow][lB * 32]);
#pragma unroll
        for (int v = 0; v < 4; ++v) {
            uint4 w = up[v];
            u2[v * 4 + 0] = *(__half2*)&w.x;
            u2[v * 4 + 1] = *(__half2*)&w.y;
            u2[v * 4 + 2] = *(__half2*)&w.z;
            u2[v * 4 + 3] = *(__half2*)&w.w;
        }
    }
    __half2 p12[16], w22[16];
    {
        const uint4* pp = (const uint4*)g_p1h2 + lB * 4;
        const uint4* wp = (const uint4*)g_w2h2 + lB * 4;
#pragma unroll
        for (int v = 0; v < 4; ++v) {
            uint4 a = __ldg(pp + v), b = __ldg(wp + v);
            p12[v * 4 + 0] = *(__half2*)&a.x; p12[v * 4 + 1] = *(__half2*)&a.y;
            p12[v * 4 + 2] = *(__half2*)&a.z; p12[v * 4 + 3] = *(__half2*)&a.w;
            w22[v * 4 + 0] = *(__half2*)&b.x; w22[v * 4 + 1] = *(__half2*)&b.y;
            w22[v * 4 + 2] = *(__half2*)&b.z; w22[v * 4 + 3] = *(__half2*)&b.w;
        }
    }

    const float b2v = b2[0];
    const int n = n_iter_ptr ? *n_iter_ptr : 20;
    const __half2 h2z = __floats2half2_rn(0.f, 0.f);

    float alpha = 0.f;
    for (int it = 0; it < n; ++it) {
        const __half2 a2h = __float2half2_rn(alpha);
        __half2 acc2a = h2z, acc2b = h2z;
#pragma unroll
        for (int q = 0; q < 16; q += 2) {
            __half2 za = __hfma2(a2h, u2[q],     p12[q]);
            __half2 zb = __hfma2(a2h, u2[q + 1], p12[q + 1]);
            acc2a = __hfma2(tanh2_fast(za), w22[q],     acc2a);
            acc2b = __hfma2(tanh2_fast(zb), w22[q + 1], acc2b);
        }
        __half2 acc2 = __hadd2(acc2a, acc2b);
        float accf = __low2float(acc2) + __high2float(acc2);
        accf += __shfl_xor_sync(0xffffffffu, accf, 1);
        accf += __shfl_xor_sync(0xffffffffu, accf, 2);
        accf += __shfl_xor_sync(0xffffffffu, accf, 4);
        alpha += 0.05f * (1.0f + tanh_fast(accf + b2v));
    }

    // tail: r reload, norm, sigmoid, output (lane owns dims 16*lB..16*lB+15)
    const float4* rv4 = (const float4*)(r + (size_t)row * D_DIM) + lB * 4;
    float4 rv[4];
    float ss = 0.f;
#pragma unroll
    for (int j = 0; j < 4; ++j) {
        rv[j] = rv4[j];
        ss = fmaf(rv[j].x, rv[j].x, fmaf(rv[j].y, rv[j].y,
             fmaf(rv[j].z, rv[j].z, fmaf(rv[j].w, rv[j].w, ss))));
    }
    ss += __shfl_xor_sync(0xffffffffu, ss, 1);
    ss += __shfl_xor_sync(0xffffffffu, ss, 2);
    ss += __shfl_xor_sync(0xffffffffu, ss, 4);
    const float inv_norm = rsqrtf(ss);

    const float sv = s_in[row];
    const float sig = 1.0f / (1.0f + __expf(-sv));
    const float fscale = sig * alpha * inv_norm;

    const float4* pv4 = (const float4*)pivot + lB * 4;
    float4* ov4 = (float4*)(out + (size_t)row * D_DIM) + lB * 4;
#pragma unroll
    for (int jj = 0; jj < 4; ++jj) {
        float4 pv = pv4[jj];
        float4 o;
        o.x = fmaf(fscale, rv[jj].x, pv.x);
        o.y = fmaf(fscale, rv[jj].y, pv.y);
        o.z = fmaf(fscale, rv[jj].z, pv.z);
        o.w = fmaf(fscale, rv[jj].w, pv.w);
        ov4[jj] = o;
    }
}

extern "C" void kernel_launch(void* const* d_in, const int* in_sizes, int n_in,
                              void* d_out, int out_size) {
    const float* r     = (const float*)d_in[0];   // [B,128]
    const float* s     = (const float*)d_in[1];   // [B,1]
    const float* pivot = (const float*)d_in[2];   // [128]
    const float* W1    = (const float*)d_in[3];   // [128,256]
    const float* b1    = (const float*)d_in[4];   // [256]
    const float* w2    = (const float*)d_in[5];   // [256]
    const float* b2    = (const float*)d_in[6];   // [1]
    const int* n_iter  = (n_in > 7) ? (const int*)d_in[7] : nullptr;
    float* out = (float*)d_out;

    const int B = in_sizes[0] / D_DIM;

    prep_kernel<<<9, 1024>>>(pivot, W1, b1, w2);

    const int blocks = (B + 31) / 32;
    main_kernel<<<blocks, 256>>>(r, s, pivot, b2, n_iter, out, B);
}